// round 2
// baseline (speedup 1.0000x reference)
#include <cuda_runtime.h>
#include <cuda_bf16.h>
#include <cstdint>

#define N_NODES 100000
#define E_MAX   3200000

// ---------------- scratch (device globals; no allocation allowed) ------------
__device__ __align__(16) float g_h1 [N_NODES * 16];   // layer1 W-transformed features
__device__ __align__(16) float g_acc[N_NODES * 16];   // layer1 weighted accum
__device__ __align__(16) float g_x2 [N_NODES * 16];   // relu(layer1 out) = layer2 input
__device__ __align__(16) float g_h2 [N_NODES * 10];   // layer2 W-transformed features
__device__ __align__(16) float g_acc2[N_NODES * 12];  // layer2 accum, padded stride 12
__device__ float g_as [N_NODES], g_ad [N_NODES], g_m [N_NODES], g_den [N_NODES];
__device__ float g_as2[N_NODES], g_ad2[N_NODES], g_m2[N_NODES], g_den2[N_NODES];
__device__ int   g_src[E_MAX], g_dst[E_MAX];
__device__ int   g_is64;   // 1 if edge_index buffer is int64, 0 if int32

// ---------------- helpers ----------------------------------------------------
__device__ __forceinline__ float lrelu(float v) { return v > 0.f ? v : 0.2f * v; }

__device__ __forceinline__ void atomicMaxFloat(float* addr, float val) {
    if (val >= 0.f)
        atomicMax(reinterpret_cast<int*>(addr), __float_as_int(val));
    else
        atomicMin(reinterpret_cast<unsigned int*>(addr), __float_as_uint(val));
}

__device__ __forceinline__ void red_add_v4(float* a, float x, float y, float z, float w) {
    asm volatile("red.global.add.v4.f32 [%0], {%1,%2,%3,%4};"
                 :: "l"(a), "f"(x), "f"(y), "f"(z), "f"(w) : "memory");
}
__device__ __forceinline__ void red_add_v2(float* a, float x, float y) {
    asm volatile("red.global.add.v2.f32 [%0], {%1,%2};"
                 :: "l"(a), "f"(x), "f"(y) : "memory");
}

// ---------------- kernels ----------------------------------------------------

// Detect int64 vs int32 edge buffer: for int64 (values < 2^17) every odd 32-bit
// word is 0. Scan first 4096 words of the buffer (well inside either layout).
__global__ void k_detect(const unsigned int* __restrict__ w) {
    __shared__ int nz;
    if (threadIdx.x == 0) nz = 0;
    __syncthreads();
    int t = threadIdx.x;
    int local = 0;
    for (int i = t; i < 4096; i += 256)
        if ((i & 1) && w[i] != 0u) local = 1;
    if (local) atomicOr(&nz, 1);
    __syncthreads();
    if (t == 0) g_is64 = (nz == 0) ? 1 : 0;
}

// decode edge_index (either dtype) -> int32 src/dst, masked into range
__global__ void k_edges(const unsigned int* __restrict__ w, int E) {
    int e = blockIdx.x * blockDim.x + threadIdx.x;
    if (e >= E) return;
    int s, d;
    if (g_is64) {
        s = (int)w[2 * e];
        d = (int)w[2 * (E + e)];
    } else {
        s = (int)w[e];
        d = (int)w[E + e];
    }
    // defensive clamp: never out of [0, N)
    s = (s < 0) ? 0 : (s >= N_NODES ? N_NODES - 1 : s);
    d = (d < 0) ? 0 : (d >= N_NODES ? N_NODES - 1 : d);
    g_src[e] = s;
    g_dst[e] = d;
}

// h1 = x @ W1  (N x 128 @ 128 x 16), tiled: 32 nodes per 256-thread block
__global__ __launch_bounds__(256) void k_gemm1(const float* __restrict__ x,
                                               const float* __restrict__ W) {
    __shared__ float xs[32 * 128];
    __shared__ float ws[128 * 16];
    int t = threadIdx.x;
    int base = blockIdx.x * 32;
    for (int i = t; i < 128 * 16; i += 256) ws[i] = W[i];
    for (int i = t; i < 32 * 128; i += 256) {
        int node = base + (i >> 7);
        xs[i] = (node < N_NODES) ? x[(size_t)base * 128 + i] : 0.f;
    }
    __syncthreads();
    for (int o = t; o < 512; o += 256) {
        int ln = o >> 4, c = o & 15;
        int node = base + ln;
        if (node >= N_NODES) continue;
        float acc = 0.f;
        #pragma unroll 16
        for (int k = 0; k < 128; k++) acc += xs[ln * 128 + k] * ws[k * 16 + c];
        g_h1[node * 16 + c] = acc;
    }
}

// per node: asrc, adst, init m with self-loop score
__global__ void k_prep1(const float* __restrict__ a_s, const float* __restrict__ a_d) {
    int n = blockIdx.x * blockDim.x + threadIdx.x;
    if (n >= N_NODES) return;
    const float4* hp = (const float4*)&g_h1[n * 16];
    float as = 0.f, ad = 0.f;
    #pragma unroll
    for (int i = 0; i < 4; i++) {
        float4 h = hp[i];
        as += h.x * a_s[4*i] + h.y * a_s[4*i+1] + h.z * a_s[4*i+2] + h.w * a_s[4*i+3];
        ad += h.x * a_d[4*i] + h.y * a_d[4*i+1] + h.z * a_d[4*i+2] + h.w * a_d[4*i+3];
    }
    g_as[n] = as; g_ad[n] = ad;
    g_m[n] = lrelu(as + ad);   // self-loop score seeds the max
}

__global__ void k_emax1(int E) {
    int e = blockIdx.x * blockDim.x + threadIdx.x;
    if (e >= E) return;
    int s = g_src[e], d = g_dst[e];
    atomicMaxFloat(&g_m[d], lrelu(g_as[s] + g_ad[d]));
}

// per node: init denom/acc with the self-loop contribution
__global__ void k_init1() {
    int n = blockIdx.x * blockDim.x + threadIdx.x;
    if (n >= N_NODES) return;
    float w = __expf(lrelu(g_as[n] + g_ad[n]) - g_m[n]);
    g_den[n] = w;
    const float4* hp = (const float4*)&g_h1[n * 16];
    float4* ap = (float4*)&g_acc[n * 16];
    #pragma unroll
    for (int i = 0; i < 4; i++) {
        float4 h = hp[i];
        ap[i] = make_float4(w * h.x, w * h.y, w * h.z, w * h.w);
    }
}

__global__ void k_eacc1(int E) {
    int e = blockIdx.x * blockDim.x + threadIdx.x;
    if (e >= E) return;
    int s = g_src[e], d = g_dst[e];
    float w = __expf(lrelu(g_as[s] + g_ad[d]) - g_m[d]);
    atomicAdd(&g_den[d], w);
    const float4* hp = (const float4*)&g_h1[s * 16];
    float* ap = &g_acc[d * 16];
    #pragma unroll
    for (int i = 0; i < 4; i++) {
        float4 h = hp[i];
        red_add_v4(ap + 4 * i, w * h.x, w * h.y, w * h.z, w * h.w);
    }
}

// out1 = relu(acc/den + b1) -> g_x2
__global__ void k_final1(const float* __restrict__ b1) {
    int n = blockIdx.x * blockDim.x + threadIdx.x;
    if (n >= N_NODES) return;
    float inv = 1.f / g_den[n];
    #pragma unroll
    for (int c = 0; c < 16; c++) {
        float v = g_acc[n * 16 + c] * inv + b1[c];
        g_x2[n * 16 + c] = v > 0.f ? v : 0.f;
    }
}

// h2 = x2 @ W2 (16 -> 10), fused with asrc2/adst2/m2 init
__global__ __launch_bounds__(256) void k_gemm2(const float* __restrict__ W2,
                                               const float* __restrict__ a2s,
                                               const float* __restrict__ a2d) {
    __shared__ float ws[160], sas[10], sad[10];
    int t = threadIdx.x;
    if (t < 160) ws[t] = W2[t];
    if (t < 10) { sas[t] = a2s[t]; sad[t] = a2d[t]; }
    __syncthreads();
    int n = blockIdx.x * blockDim.x + t;
    if (n >= N_NODES) return;
    const float4* xp = (const float4*)&g_x2[n * 16];
    float hin[16];
    #pragma unroll
    for (int i = 0; i < 4; i++) {
        float4 v = xp[i];
        hin[4*i] = v.x; hin[4*i+1] = v.y; hin[4*i+2] = v.z; hin[4*i+3] = v.w;
    }
    float as = 0.f, ad = 0.f;
    #pragma unroll
    for (int j = 0; j < 10; j++) {
        float a = 0.f;
        #pragma unroll
        for (int k = 0; k < 16; k++) a += hin[k] * ws[k * 10 + j];
        g_h2[n * 10 + j] = a;
        as += a * sas[j]; ad += a * sad[j];
    }
    g_as2[n] = as; g_ad2[n] = ad;
    g_m2[n] = lrelu(as + ad);
}

__global__ void k_emax2(int E) {
    int e = blockIdx.x * blockDim.x + threadIdx.x;
    if (e >= E) return;
    int s = g_src[e], d = g_dst[e];
    atomicMaxFloat(&g_m2[d], lrelu(g_as2[s] + g_ad2[d]));
}

__global__ void k_init2() {
    int n = blockIdx.x * blockDim.x + threadIdx.x;
    if (n >= N_NODES) return;
    float w = __expf(lrelu(g_as2[n] + g_ad2[n]) - g_m2[n]);
    g_den2[n] = w;
    #pragma unroll
    for (int c = 0; c < 10; c++) g_acc2[n * 12 + c] = w * g_h2[n * 10 + c];
}

__global__ void k_eacc2(int E) {
    int e = blockIdx.x * blockDim.x + threadIdx.x;
    if (e >= E) return;
    int s = g_src[e], d = g_dst[e];
    float w = __expf(lrelu(g_as2[s] + g_ad2[d]) - g_m2[d]);
    atomicAdd(&g_den2[d], w);
    const float2* hp = (const float2*)&g_h2[s * 10];   // 8B aligned (stride 40B)
    float2 h0 = hp[0], h1 = hp[1], h2 = hp[2], h3 = hp[3], h4 = hp[4];
    float* ap = &g_acc2[d * 12];                        // 48B stride -> 16B aligned
    red_add_v4(ap,     w * h0.x, w * h0.y, w * h1.x, w * h1.y);
    red_add_v4(ap + 4, w * h2.x, w * h2.y, w * h3.x, w * h3.y);
    red_add_v2(ap + 8, w * h4.x, w * h4.y);
}

// final: gat2 out (+b2, no relu) -> Wl1+bl1 -> relu -> Wl2+bl2 -> d_out[N]
__global__ __launch_bounds__(256) void k_final2(const float* __restrict__ b2,
                                                const float* __restrict__ Wl1,
                                                const float* __restrict__ bl1,
                                                const float* __restrict__ Wl2,
                                                const float* __restrict__ bl2,
                                                float* __restrict__ out) {
    __shared__ float swl1[100], sbl1[10], swl2[10], sb2[10];
    int t = threadIdx.x;
    if (t < 100) swl1[t] = Wl1[t];
    if (t < 10) { sbl1[t] = bl1[t]; swl2[t] = Wl2[t]; sb2[t] = b2[t]; }
    __syncthreads();
    int n = blockIdx.x * blockDim.x + t;
    if (n >= N_NODES) return;
    float inv = 1.f / g_den2[n];
    float g[10];
    #pragma unroll
    for (int c = 0; c < 10; c++) g[c] = g_acc2[n * 12 + c] * inv + sb2[c];
    float y = 0.f;
    #pragma unroll
    for (int j = 0; j < 10; j++) {
        float v = sbl1[j];
        #pragma unroll
        for (int c = 0; c < 10; c++) v += g[c] * swl1[c * 10 + j];
        v = v > 0.f ? v : 0.f;
        y += v * swl2[j];
    }
    out[n] = y + bl2[0];
}

// ---------------- launch ------------------------------------------------------
extern "C" void kernel_launch(void* const* d_in, const int* in_sizes, int n_in,
                              void* d_out, int out_size) {
    const float*        x    = (const float*)d_in[0];
    const unsigned int* ei   = (const unsigned int*)d_in[1];
    const float*        W1   = (const float*)d_in[2];
    const float*        a1s  = (const float*)d_in[3];
    const float*        a1d  = (const float*)d_in[4];
    const float*        b1   = (const float*)d_in[5];
    const float*        W2   = (const float*)d_in[6];
    const float*        a2s  = (const float*)d_in[7];
    const float*        a2d  = (const float*)d_in[8];
    const float*        b2   = (const float*)d_in[9];
    const float*        Wl1  = (const float*)d_in[10];
    const float*        bl1  = (const float*)d_in[11];
    const float*        Wl2  = (const float*)d_in[12];
    const float*        bl2  = (const float*)d_in[13];
    float*              out  = (float*)d_out;

    int E = in_sizes[1] / 2;
    if (E > E_MAX) E = E_MAX;
    const int N = N_NODES;
    int nb_n = (N + 255) / 256;
    int nb_e = (E + 255) / 256;

    k_detect<<<1, 256>>>(ei);
    k_edges <<<nb_e, 256>>>(ei, E);
    k_gemm1 <<<(N + 31) / 32, 256>>>(x, W1);
    k_prep1 <<<nb_n, 256>>>(a1s, a1d);
    k_emax1 <<<nb_e, 256>>>(E);
    k_init1 <<<nb_n, 256>>>();
    k_eacc1 <<<nb_e, 256>>>(E);
    k_final1<<<nb_n, 256>>>(b1);
    k_gemm2 <<<nb_n, 256>>>(W2, a2s, a2d);
    k_emax2 <<<nb_e, 256>>>(E);
    k_init2 <<<nb_n, 256>>>();
    k_eacc2 <<<nb_e, 256>>>(E);
    k_final2<<<nb_n, 256>>>(b2, Wl1, bl1, Wl2, bl2, out);
}

// round 3
// speedup vs baseline: 1.1236x; 1.1236x over previous
#include <cuda_runtime.h>
#include <cuda_bf16.h>
#include <cstdint>

#define N_NODES 100000
#define E_MAX   3200000
#define NBLK_N  ((N_NODES + 255) / 256)   // 391

// ---------------- scratch (device globals) -----------------------------------
__device__ __align__(16) float g_h1 [N_NODES * 16];
__device__ __align__(16) float g_x2 [N_NODES * 16];
__device__ __align__(16) float g_h2 [N_NODES * 10];
__device__ float g_as [N_NODES], g_ad [N_NODES];
__device__ float g_as2[N_NODES], g_ad2[N_NODES];
__device__ int   g_src[E_MAX], g_dst[E_MAX];
__device__ int   g_esrc[E_MAX];            // CSR: src sorted by dst
__device__ int   g_off[N_NODES + 1];       // CSR row offsets
__device__ int   g_cur[N_NODES];           // scatter cursors
__device__ int   g_deg[N_NODES];
__device__ int   g_bsum[512];
__device__ int   g_is64;

// ---------------- helpers ----------------------------------------------------
__device__ __forceinline__ float lrelu(float v) { return v > 0.f ? v : 0.2f * v; }

// ---------------- edge decode ------------------------------------------------
__global__ void k_detect(const unsigned int* __restrict__ w) {
    __shared__ int nz;
    if (threadIdx.x == 0) nz = 0;
    __syncthreads();
    int local = 0;
    for (int i = threadIdx.x; i < 4096; i += 256)
        if ((i & 1) && w[i] != 0u) local = 1;
    if (local) atomicOr(&nz, 1);
    __syncthreads();
    if (threadIdx.x == 0) g_is64 = (nz == 0) ? 1 : 0;
}

__global__ void k_edges(const unsigned int* __restrict__ w, int E) {
    int e = blockIdx.x * blockDim.x + threadIdx.x;
    if (e >= E) return;
    int s, d;
    if (g_is64) { s = (int)w[2 * e]; d = (int)w[2 * (E + e)]; }
    else        { s = (int)w[e];     d = (int)w[E + e]; }
    s = (s < 0) ? 0 : (s >= N_NODES ? N_NODES - 1 : s);
    d = (d < 0) ? 0 : (d >= N_NODES ? N_NODES - 1 : d);
    g_src[e] = s;
    g_dst[e] = d;
}

// ---------------- CSR build --------------------------------------------------
__global__ void k_zero() {
    int n = blockIdx.x * blockDim.x + threadIdx.x;
    if (n < N_NODES) g_deg[n] = 0;
}

__global__ void k_hist(int E) {
    int e = blockIdx.x * blockDim.x + threadIdx.x;
    if (e < E) atomicAdd(&g_deg[g_dst[e]], 1);
}

// per-block exclusive scan of degrees; block totals to g_bsum
__global__ __launch_bounds__(256) void k_scan_block() {
    __shared__ int s[256];
    int t = threadIdx.x;
    int i = blockIdx.x * 256 + t;
    int v = (i < N_NODES) ? g_deg[i] : 0;
    s[t] = v;
    __syncthreads();
    #pragma unroll
    for (int o = 1; o < 256; o <<= 1) {
        int u = (t >= o) ? s[t - o] : 0;
        __syncthreads();
        s[t] += u;
        __syncthreads();
    }
    if (i < N_NODES) g_off[i] = s[t] - v;
    if (t == 255) g_bsum[blockIdx.x] = s[255];
}

// single-block exclusive scan of the 391 block sums
__global__ __launch_bounds__(512) void k_scan_top() {
    __shared__ int s[512];
    int t = threadIdx.x;
    int v = (t < NBLK_N) ? g_bsum[t] : 0;
    s[t] = v;
    __syncthreads();
    #pragma unroll
    for (int o = 1; o < 512; o <<= 1) {
        int u = (t >= o) ? s[t - o] : 0;
        __syncthreads();
        s[t] += u;
        __syncthreads();
    }
    if (t < NBLK_N) g_bsum[t] = s[t] - v;
}

__global__ void k_scan_add(int E) {
    int i = blockIdx.x * blockDim.x + threadIdx.x;
    if (i < N_NODES) {
        int v = g_off[i] + g_bsum[blockIdx.x * 256 / 256 == 0 ? blockIdx.x : blockIdx.x]; // blockIdx maps 1:1
        v = g_off[i] + g_bsum[blockIdx.x];
        g_off[i] = v;
        g_cur[i] = v;
    }
    if (i == 0) g_off[N_NODES] = E;
}

__global__ void k_scatter(int E) {
    int e = blockIdx.x * blockDim.x + threadIdx.x;
    if (e >= E) return;
    int d = g_dst[e];
    int pos = atomicAdd(&g_cur[d], 1);
    g_esrc[pos] = g_src[e];
}

// ---------------- dense layers -----------------------------------------------
// h1 = x @ W1 (N x 128 @ 128 x 16)
__global__ __launch_bounds__(256) void k_gemm1(const float* __restrict__ x,
                                               const float* __restrict__ W) {
    __shared__ float xs[32 * 128];
    __shared__ float ws[128 * 16];
    int t = threadIdx.x;
    int base = blockIdx.x * 32;
    for (int i = t; i < 128 * 16; i += 256) ws[i] = W[i];
    for (int i = t; i < 32 * 128; i += 256) {
        int node = base + (i >> 7);
        xs[i] = (node < N_NODES) ? x[(size_t)base * 128 + i] : 0.f;
    }
    __syncthreads();
    for (int o = t; o < 512; o += 256) {
        int ln = o >> 4, c = o & 15;
        int node = base + ln;
        if (node >= N_NODES) continue;
        float acc = 0.f;
        #pragma unroll 16
        for (int k = 0; k < 128; k++) acc += xs[ln * 128 + k] * ws[k * 16 + c];
        g_h1[node * 16 + c] = acc;
    }
}

__global__ void k_prep1(const float* __restrict__ a_s, const float* __restrict__ a_d) {
    int n = blockIdx.x * blockDim.x + threadIdx.x;
    if (n >= N_NODES) return;
    const float4* hp = (const float4*)&g_h1[n * 16];
    float as = 0.f, ad = 0.f;
    #pragma unroll
    for (int i = 0; i < 4; i++) {
        float4 h = hp[i];
        as += h.x * a_s[4*i] + h.y * a_s[4*i+1] + h.z * a_s[4*i+2] + h.w * a_s[4*i+3];
        ad += h.x * a_d[4*i] + h.y * a_d[4*i+1] + h.z * a_d[4*i+2] + h.w * a_d[4*i+3];
    }
    g_as[n] = as; g_ad[n] = ad;
}

// ---------------- GAT layer 1: warp per destination ---------------------------
__global__ __launch_bounds__(256) void k_layer1(const float* __restrict__ b1) {
    __shared__ float sb1[16];
    if (threadIdx.x < 16) sb1[threadIdx.x] = b1[threadIdx.x];
    __syncthreads();
    int warp = (blockIdx.x * 256 + threadIdx.x) >> 5;
    int lane = threadIdx.x & 31;
    if (warp >= N_NODES) return;
    int beg = g_off[warp], end = g_off[warp + 1];
    float ad = g_ad[warp];
    float eself = lrelu(g_as[warp] + ad);
    // pass A: per-dst max
    float m = eself;
    for (int i = beg + lane; i < end; i += 32)
        m = fmaxf(m, lrelu(g_as[g_esrc[i]] + ad));
    #pragma unroll
    for (int o = 16; o; o >>= 1) m = fmaxf(m, __shfl_xor_sync(0xffffffffu, m, o));
    // pass B: accumulate
    float wsum = 0.f;
    float acc[16];
    #pragma unroll
    for (int c = 0; c < 16; c++) acc[c] = 0.f;
    if (lane == 0) {
        float w = __expf(eself - m);
        wsum = w;
        const float4* hp = (const float4*)&g_h1[warp * 16];
        #pragma unroll
        for (int j = 0; j < 4; j++) {
            float4 h = hp[j];
            acc[4*j] = w*h.x; acc[4*j+1] = w*h.y; acc[4*j+2] = w*h.z; acc[4*j+3] = w*h.w;
        }
    }
    for (int i = beg + lane; i < end; i += 32) {
        int s = g_esrc[i];
        float w = __expf(lrelu(g_as[s] + ad) - m);
        wsum += w;
        const float4* hp = (const float4*)&g_h1[s * 16];
        #pragma unroll
        for (int j = 0; j < 4; j++) {
            float4 h = hp[j];
            acc[4*j] += w*h.x; acc[4*j+1] += w*h.y; acc[4*j+2] += w*h.z; acc[4*j+3] += w*h.w;
        }
    }
    #pragma unroll
    for (int o = 16; o; o >>= 1) {
        wsum += __shfl_xor_sync(0xffffffffu, wsum, o);
        #pragma unroll
        for (int c = 0; c < 16; c++) acc[c] += __shfl_xor_sync(0xffffffffu, acc[c], o);
    }
    if (lane == 0) {
        float inv = 1.f / wsum;
        #pragma unroll
        for (int c = 0; c < 16; c++) {
            float v = acc[c] * inv + sb1[c];
            g_x2[warp * 16 + c] = v > 0.f ? v : 0.f;
        }
    }
}

// h2 = x2 @ W2 (16 -> 10) + asrc2/adst2
__global__ __launch_bounds__(256) void k_gemm2(const float* __restrict__ W2,
                                               const float* __restrict__ a2s,
                                               const float* __restrict__ a2d) {
    __shared__ float ws[160], sas[10], sad[10];
    int t = threadIdx.x;
    if (t < 160) ws[t] = W2[t];
    if (t < 10) { sas[t] = a2s[t]; sad[t] = a2d[t]; }
    __syncthreads();
    int n = blockIdx.x * blockDim.x + t;
    if (n >= N_NODES) return;
    const float4* xp = (const float4*)&g_x2[n * 16];
    float hin[16];
    #pragma unroll
    for (int i = 0; i < 4; i++) {
        float4 v = xp[i];
        hin[4*i] = v.x; hin[4*i+1] = v.y; hin[4*i+2] = v.z; hin[4*i+3] = v.w;
    }
    float as = 0.f, ad = 0.f;
    #pragma unroll
    for (int j = 0; j < 10; j++) {
        float a = 0.f;
        #pragma unroll
        for (int k = 0; k < 16; k++) a += hin[k] * ws[k * 10 + j];
        g_h2[n * 10 + j] = a;
        as += a * sas[j]; ad += a * sad[j];
    }
    g_as2[n] = as; g_ad2[n] = ad;
}

// ---------------- GAT layer 2 + fused output MLP ------------------------------
__global__ __launch_bounds__(256) void k_layer2(const float* __restrict__ b2,
                                                const float* __restrict__ Wl1,
                                                const float* __restrict__ bl1,
                                                const float* __restrict__ Wl2,
                                                const float* __restrict__ bl2,
                                                float* __restrict__ out) {
    __shared__ float swl1[100], sbl1[10], swl2[10], sb2[10], sbl2;
    int t = threadIdx.x;
    if (t < 100) swl1[t] = Wl1[t];
    if (t < 10) { sbl1[t] = bl1[t]; swl2[t] = Wl2[t]; sb2[t] = b2[t]; }
    if (t == 0) sbl2 = bl2[0];
    __syncthreads();
    int warp = (blockIdx.x * 256 + t) >> 5;
    int lane = t & 31;
    if (warp >= N_NODES) return;
    int beg = g_off[warp], end = g_off[warp + 1];
    float ad = g_ad2[warp];
    float eself = lrelu(g_as2[warp] + ad);
    float m = eself;
    for (int i = beg + lane; i < end; i += 32)
        m = fmaxf(m, lrelu(g_as2[g_esrc[i]] + ad));
    #pragma unroll
    for (int o = 16; o; o >>= 1) m = fmaxf(m, __shfl_xor_sync(0xffffffffu, m, o));
    float wsum = 0.f;
    float acc[10];
    #pragma unroll
    for (int c = 0; c < 10; c++) acc[c] = 0.f;
    if (lane == 0) {
        float w = __expf(eself - m);
        wsum = w;
        #pragma unroll
        for (int c = 0; c < 10; c++) acc[c] = w * g_h2[warp * 10 + c];
    }
    for (int i = beg + lane; i < end; i += 32) {
        int s = g_esrc[i];
        float w = __expf(lrelu(g_as2[s] + ad) - m);
        wsum += w;
        const float2* hp = (const float2*)&g_h2[s * 10];  // 8B aligned (stride 40B)
        float2 h0 = hp[0], h1 = hp[1], h2v = hp[2], h3 = hp[3], h4 = hp[4];
        acc[0]+=w*h0.x; acc[1]+=w*h0.y; acc[2]+=w*h1.x; acc[3]+=w*h1.y;
        acc[4]+=w*h2v.x; acc[5]+=w*h2v.y; acc[6]+=w*h3.x; acc[7]+=w*h3.y;
        acc[8]+=w*h4.x; acc[9]+=w*h4.y;
    }
    #pragma unroll
    for (int o = 16; o; o >>= 1) {
        wsum += __shfl_xor_sync(0xffffffffu, wsum, o);
        #pragma unroll
        for (int c = 0; c < 10; c++) acc[c] += __shfl_xor_sync(0xffffffffu, acc[c], o);
    }
    if (lane == 0) {
        float inv = 1.f / wsum;
        float g[10];
        #pragma unroll
        for (int c = 0; c < 10; c++) g[c] = acc[c] * inv + sb2[c];
        float y = 0.f;
        #pragma unroll
        for (int j = 0; j < 10; j++) {
            float v = sbl1[j];
            #pragma unroll
            for (int c = 0; c < 10; c++) v += g[c] * swl1[c * 10 + j];
            v = v > 0.f ? v : 0.f;
            y += v * swl2[j];
        }
        out[warp] = y + sbl2;
    }
}

// ---------------- launch ------------------------------------------------------
extern "C" void kernel_launch(void* const* d_in, const int* in_sizes, int n_in,
                              void* d_out, int out_size) {
    const float*        x    = (const float*)d_in[0];
    const unsigned int* ei   = (const unsigned int*)d_in[1];
    const float*        W1   = (const float*)d_in[2];
    const float*        a1s  = (const float*)d_in[3];
    const float*        a1d  = (const float*)d_in[4];
    const float*        b1   = (const float*)d_in[5];
    const float*        W2   = (const float*)d_in[6];
    const float*        a2s  = (const float*)d_in[7];
    const float*        a2d  = (const float*)d_in[8];
    const float*        b2   = (const float*)d_in[9];
    const float*        Wl1  = (const float*)d_in[10];
    const float*        bl1  = (const float*)d_in[11];
    const float*        Wl2  = (const float*)d_in[12];
    const float*        bl2  = (const float*)d_in[13];
    float*              out  = (float*)d_out;

    int E = in_sizes[1] / 2;
    if (E > E_MAX) E = E_MAX;
    int nb_e = (E + 255) / 256;
    int nb_w = (N_NODES * 32 + 255) / 256;   // warp-per-node grids

    // edge decode + CSR build
    k_detect    <<<1, 256>>>(ei);
    k_edges     <<<nb_e, 256>>>(ei, E);
    k_zero      <<<NBLK_N, 256>>>();
    k_hist      <<<nb_e, 256>>>(E);
    k_scan_block<<<NBLK_N, 256>>>();
    k_scan_top  <<<1, 512>>>();
    k_scan_add  <<<NBLK_N, 256>>>(E);
    k_scatter   <<<nb_e, 256>>>(E);

    // dense + GAT layers
    k_gemm1 <<<(N_NODES + 31) / 32, 256>>>(x, W1);
    k_prep1 <<<NBLK_N, 256>>>(a1s, a1d);
    k_layer1<<<nb_w, 256>>>(b1);
    k_gemm2 <<<NBLK_N, 256>>>(W2, a2s, a2d);
    k_layer2<<<nb_w, 256>>>(b2, Wl1, bl1, Wl2, bl2, out);
}

// round 5
// speedup vs baseline: 1.2051x; 1.0725x over previous
#include <cuda_runtime.h>
#include <cuda_bf16.h>
#include <cstdint>
#include <cfloat>

#define N_NODES 100000
#define E_MAX   3200000
#define NBLK_N  ((N_NODES + 255) / 256)   // 391

// ---------------- scratch (device globals) -----------------------------------
__device__ __align__(16) float g_h1 [N_NODES * 16];
__device__ __align__(16) float g_x2 [N_NODES * 16];
__device__ __align__(16) float g_h2p[N_NODES * 12];  // h2 (10) + as2 at [10], pad [11]
__device__ float g_as [N_NODES], g_ad [N_NODES];
__device__ float g_ad2[N_NODES];
__device__ int   g_src[E_MAX], g_dst[E_MAX];
__device__ int   g_esrc[E_MAX];            // CSR: src sorted by dst
__device__ int   g_off[N_NODES + 1];       // CSR row offsets
__device__ int   g_cur[N_NODES];           // scatter cursors
__device__ int   g_deg[N_NODES];
__device__ int   g_bsum[512];
__device__ int   g_is64;

// ---------------- helpers ----------------------------------------------------
__device__ __forceinline__ float lrelu(float v) { return v > 0.f ? v : 0.2f * v; }

// ---------------- edge decode + fused histogram -------------------------------
__global__ void k_detect(const unsigned int* __restrict__ w) {
    __shared__ int nz;
    if (threadIdx.x == 0) nz = 0;
    __syncthreads();
    int local = 0;
    for (int i = threadIdx.x; i < 4096; i += 256)
        if ((i & 1) && w[i] != 0u) local = 1;
    if (local) atomicOr(&nz, 1);
    __syncthreads();
    if (threadIdx.x == 0) g_is64 = (nz == 0) ? 1 : 0;
}

__global__ void k_zero() {
    int n = blockIdx.x * blockDim.x + threadIdx.x;
    if (n < N_NODES) g_deg[n] = 0;
}

__global__ void k_edges(const unsigned int* __restrict__ w, int E) {
    int e = blockIdx.x * blockDim.x + threadIdx.x;
    if (e >= E) return;
    int s, d;
    if (g_is64) { s = (int)w[2 * e]; d = (int)w[2 * (E + e)]; }
    else        { s = (int)w[e];     d = (int)w[E + e]; }
    s = (s < 0) ? 0 : (s >= N_NODES ? N_NODES - 1 : s);
    d = (d < 0) ? 0 : (d >= N_NODES ? N_NODES - 1 : d);
    g_src[e] = s;
    g_dst[e] = d;
    atomicAdd(&g_deg[d], 1);               // fused histogram
}

// ---------------- CSR build --------------------------------------------------
__global__ __launch_bounds__(256) void k_scan_block() {
    __shared__ int s[256];
    int t = threadIdx.x;
    int i = blockIdx.x * 256 + t;
    int v = (i < N_NODES) ? g_deg[i] : 0;
    s[t] = v;
    __syncthreads();
    #pragma unroll
    for (int o = 1; o < 256; o <<= 1) {
        int u = (t >= o) ? s[t - o] : 0;
        __syncthreads();
        s[t] += u;
        __syncthreads();
    }
    if (i < N_NODES) g_off[i] = s[t] - v;
    if (t == 255) g_bsum[blockIdx.x] = s[255];
}

__global__ __launch_bounds__(512) void k_scan_top() {
    __shared__ int s[512];
    int t = threadIdx.x;
    int v = (t < NBLK_N) ? g_bsum[t] : 0;
    s[t] = v;
    __syncthreads();
    #pragma unroll
    for (int o = 1; o < 512; o <<= 1) {
        int u = (t >= o) ? s[t - o] : 0;
        __syncthreads();
        s[t] += u;
        __syncthreads();
    }
    if (t < NBLK_N) g_bsum[t] = s[t] - v;
}

__global__ void k_scan_add(int E) {
    int i = blockIdx.x * blockDim.x + threadIdx.x;
    if (i < N_NODES) {
        int v = g_off[i] + g_bsum[blockIdx.x];
        g_off[i] = v;
        g_cur[i] = v;
    }
    if (i == 0) g_off[N_NODES] = E;
}

__global__ void k_scatter(int E) {
    int e = blockIdx.x * blockDim.x + threadIdx.x;
    if (e >= E) return;
    int d = g_dst[e];
    int pos = atomicAdd(&g_cur[d], 1);
    g_esrc[pos] = g_src[e];
}

// ---------------- dense layers -----------------------------------------------
// h1 = x @ W1 (N x 128 @ 128 x 16)
__global__ __launch_bounds__(256) void k_gemm1(const float* __restrict__ x,
                                               const float* __restrict__ W) {
    __shared__ float xs[32 * 128];
    __shared__ float ws[128 * 16];
    int t = threadIdx.x;
    int base = blockIdx.x * 32;
    for (int i = t; i < 128 * 16; i += 256) ws[i] = W[i];
    for (int i = t; i < 32 * 128; i += 256) {
        int node = base + (i >> 7);
        xs[i] = (node < N_NODES) ? x[(size_t)base * 128 + i] : 0.f;
    }
    __syncthreads();
    for (int o = t; o < 512; o += 256) {
        int ln = o >> 4, c = o & 15;
        int node = base + ln;
        if (node >= N_NODES) continue;
        float acc = 0.f;
        #pragma unroll 16
        for (int k = 0; k < 128; k++) acc += xs[ln * 128 + k] * ws[k * 16 + c];
        g_h1[node * 16 + c] = acc;
    }
}

__global__ void k_prep1(const float* __restrict__ a_s, const float* __restrict__ a_d) {
    int n = blockIdx.x * blockDim.x + threadIdx.x;
    if (n >= N_NODES) return;
    const float4* hp = (const float4*)&g_h1[n * 16];
    float as = 0.f, ad = 0.f;
    #pragma unroll
    for (int i = 0; i < 4; i++) {
        float4 h = hp[i];
        as += h.x * a_s[4*i] + h.y * a_s[4*i+1] + h.z * a_s[4*i+2] + h.w * a_s[4*i+3];
        ad += h.x * a_d[4*i] + h.y * a_d[4*i+1] + h.z * a_d[4*i+2] + h.w * a_d[4*i+3];
    }
    g_as[n] = as; g_ad[n] = ad;
}

// ---------------- GAT layer 1: warp per dst, single-pass online softmax -------
__global__ __launch_bounds__(256) void k_layer1(const float* __restrict__ b1) {
    __shared__ float sb1[16];
    if (threadIdx.x < 16) sb1[threadIdx.x] = b1[threadIdx.x];
    __syncthreads();
    int warp = (blockIdx.x * 256 + threadIdx.x) >> 5;
    int lane = threadIdx.x & 31;
    if (warp >= N_NODES) return;
    int beg = g_off[warp], end = g_off[warp + 1];
    float ad = g_ad[warp];

    float m, wsum;
    float acc[16];
    if (lane == 0) {
        m = lrelu(g_as[warp] + ad);           // self-loop seeds lane 0
        wsum = 1.f;                            // exp(eself - m) = 1
        const float4* hp = (const float4*)&g_h1[warp * 16];
        #pragma unroll
        for (int j = 0; j < 4; j++) {
            float4 h = hp[j];
            acc[4*j] = h.x; acc[4*j+1] = h.y; acc[4*j+2] = h.z; acc[4*j+3] = h.w;
        }
    } else {
        m = -FLT_MAX; wsum = 0.f;
        #pragma unroll
        for (int c = 0; c < 16; c++) acc[c] = 0.f;
    }

    for (int i = beg + lane; i < end; i += 32) {
        int s = g_esrc[i];
        float e = lrelu(g_as[s] + ad);
        float w;
        if (e > m) {
            float sc = __expf(m - e);          // m=-FLT_MAX -> sc=0
            wsum *= sc;
            #pragma unroll
            for (int c = 0; c < 16; c++) acc[c] *= sc;
            m = e; w = 1.f;
        } else {
            w = __expf(e - m);
        }
        wsum += w;
        const float4* hp = (const float4*)&g_h1[s * 16];
        #pragma unroll
        for (int j = 0; j < 4; j++) {
            float4 h = hp[j];
            acc[4*j] += w*h.x; acc[4*j+1] += w*h.y; acc[4*j+2] += w*h.z; acc[4*j+3] += w*h.w;
        }
    }

    // warp combine with rescale
    #pragma unroll
    for (int o = 16; o; o >>= 1) {
        float mo = __shfl_xor_sync(0xffffffffu, m, o);
        float wo = __shfl_xor_sync(0xffffffffu, wsum, o);
        float M  = fmaxf(m, mo);
        float sa = __expf(m - M), sb = __expf(mo - M);
        wsum = wsum * sa + wo * sb;
        #pragma unroll
        for (int c = 0; c < 16; c++) {
            float ao = __shfl_xor_sync(0xffffffffu, acc[c], o);
            acc[c] = acc[c] * sa + ao * sb;
        }
        m = M;
    }

    if (lane == 0) {
        float inv = 1.f / wsum;
        #pragma unroll
        for (int c = 0; c < 16; c++) {
            float v = acc[c] * inv + sb1[c];
            g_x2[warp * 16 + c] = v > 0.f ? v : 0.f;
        }
    }
}

// h2 = x2 @ W2 (16 -> 10); packed row: h2p[n*12 + 0..9]=h2, [10]=as2; ad2 separate
__global__ __launch_bounds__(256) void k_gemm2(const float* __restrict__ W2,
                                               const float* __restrict__ a2s,
                                               const float* __restrict__ a2d) {
    __shared__ float ws[160], sas[10], sad[10];
    int t = threadIdx.x;
    if (t < 160) ws[t] = W2[t];
    if (t < 10) { sas[t] = a2s[t]; sad[t] = a2d[t]; }
    __syncthreads();
    int n = blockIdx.x * blockDim.x + t;
    if (n >= N_NODES) return;
    const float4* xp = (const float4*)&g_x2[n * 16];
    float hin[16];
    #pragma unroll
    for (int i = 0; i < 4; i++) {
        float4 v = xp[i];
        hin[4*i] = v.x; hin[4*i+1] = v.y; hin[4*i+2] = v.z; hin[4*i+3] = v.w;
    }
    float as = 0.f, ad = 0.f;
    float hv[12];
    #pragma unroll
    for (int j = 0; j < 10; j++) {
        float a = 0.f;
        #pragma unroll
        for (int k = 0; k < 16; k++) a += hin[k] * ws[k * 10 + j];
        hv[j] = a;
        as += a * sas[j]; ad += a * sad[j];
    }
    hv[10] = as; hv[11] = 0.f;
    float4* op = (float4*)&g_h2p[n * 12];
    op[0] = make_float4(hv[0], hv[1], hv[2], hv[3]);
    op[1] = make_float4(hv[4], hv[5], hv[6], hv[7]);
    op[2] = make_float4(hv[8], hv[9], hv[10], hv[11]);
    g_ad2[n] = ad;
}

// ---------------- GAT layer 2 (single pass) + fused output MLP ----------------
__global__ __launch_bounds__(256) void k_layer2(const float* __restrict__ b2,
                                                const float* __restrict__ Wl1,
                                                const float* __restrict__ bl1,
                                                const float* __restrict__ Wl2,
                                                const float* __restrict__ bl2,
                                                float* __restrict__ out) {
    __shared__ float swl1[100], sbl1[10], swl2[10], sb2[10], sbl2;
    int t = threadIdx.x;
    if (t < 100) swl1[t] = Wl1[t];
    if (t < 10) { sbl1[t] = bl1[t]; swl2[t] = Wl2[t]; sb2[t] = b2[t]; }
    if (t == 0) sbl2 = bl2[0];
    __syncthreads();
    int warp = (blockIdx.x * 256 + t) >> 5;
    int lane = t & 31;
    if (warp >= N_NODES) return;
    int beg = g_off[warp], end = g_off[warp + 1];
    float ad = g_ad2[warp];

    float m, wsum;
    float acc[10];
    if (lane == 0) {
        const float4* hp = (const float4*)&g_h2p[warp * 12];
        float4 h0 = hp[0], h1 = hp[1], h2v = hp[2];
        m = lrelu(h2v.z + ad);                // as2 at [10] (= h2v.z)
        wsum = 1.f;
        acc[0]=h0.x; acc[1]=h0.y; acc[2]=h0.z; acc[3]=h0.w;
        acc[4]=h1.x; acc[5]=h1.y; acc[6]=h1.z; acc[7]=h1.w;
        acc[8]=h2v.x; acc[9]=h2v.y;
    } else {
        m = -FLT_MAX; wsum = 0.f;
        #pragma unroll
        for (int c = 0; c < 10; c++) acc[c] = 0.f;
    }

    for (int i = beg + lane; i < end; i += 32) {
        int s = g_esrc[i];
        const float4* hp = (const float4*)&g_h2p[s * 12];
        float4 h0 = hp[0], h1 = hp[1], h2v = hp[2];
        float e = lrelu(h2v.z + ad);
        float w;
        if (e > m) {
            float sc = __expf(m - e);
            wsum *= sc;
            #pragma unroll
            for (int c = 0; c < 10; c++) acc[c] *= sc;
            m = e; w = 1.f;
        } else {
            w = __expf(e - m);
        }
        wsum += w;
        acc[0]+=w*h0.x; acc[1]+=w*h0.y; acc[2]+=w*h0.z; acc[3]+=w*h0.w;
        acc[4]+=w*h1.x; acc[5]+=w*h1.y; acc[6]+=w*h1.z; acc[7]+=w*h1.w;
        acc[8]+=w*h2v.x; acc[9]+=w*h2v.y;
    }

    #pragma unroll
    for (int o = 16; o; o >>= 1) {
        float mo = __shfl_xor_sync(0xffffffffu, m, o);
        float wo = __shfl_xor_sync(0xffffffffu, wsum, o);
        float M  = fmaxf(m, mo);
        float sa = __expf(m - M), sb = __expf(mo - M);
        wsum = wsum * sa + wo * sb;
        #pragma unroll
        for (int c = 0; c < 10; c++) {
            float ao = __shfl_xor_sync(0xffffffffu, acc[c], o);
            acc[c] = acc[c] * sa + ao * sb;
        }
        m = M;
    }

    if (lane == 0) {
        float inv = 1.f / wsum;
        float g[10];
        #pragma unroll
        for (int c = 0; c < 10; c++) g[c] = acc[c] * inv + sb2[c];
        float y = 0.f;
        #pragma unroll
        for (int j = 0; j < 10; j++) {
            float v = sbl1[j];
            #pragma unroll
            for (int c = 0; c < 10; c++) v += g[c] * swl1[c * 10 + j];
            v = v > 0.f ? v : 0.f;
            y += v * swl2[j];
        }
        out[warp] = y + sbl2;
    }
}

// ---------------- launch ------------------------------------------------------
extern "C" void kernel_launch(void* const* d_in, const int* in_sizes, int n_in,
                              void* d_out, int out_size) {
    const float*        x    = (const float*)d_in[0];
    const unsigned int* ei   = (const unsigned int*)d_in[1];
    const float*        W1   = (const float*)d_in[2];
    const float*        a1s  = (const float*)d_in[3];
    const float*        a1d  = (const float*)d_in[4];
    const float*        b1   = (const float*)d_in[5];
    const float*        W2   = (const float*)d_in[6];
    const float*        a2s  = (const float*)d_in[7];
    const float*        a2d  = (const float*)d_in[8];
    const float*        b2   = (const float*)d_in[9];
    const float*        Wl1  = (const float*)d_in[10];
    const float*        bl1  = (const float*)d_in[11];
    const float*        Wl2  = (const float*)d_in[12];
    const float*        bl2  = (const float*)d_in[13];
    float*              out  = (float*)d_out;

    int E = in_sizes[1] / 2;
    if (E > E_MAX) E = E_MAX;
    int nb_e = (E + 255) / 256;
    int nb_w = (N_NODES * 32 + 255) / 256;   // warp-per-node grids

    k_detect    <<<1, 256>>>(ei);
    k_zero      <<<NBLK_N, 256>>>();
    k_edges     <<<nb_e, 256>>>(ei, E);      // decode + histogram
    k_scan_block<<<NBLK_N, 256>>>();
    k_scan_top  <<<1, 512>>>();
    k_scan_add  <<<NBLK_N, 256>>>(E);
    k_scatter   <<<nb_e, 256>>>(E);

    k_gemm1 <<<(N_NODES + 31) / 32, 256>>>(x, W1);
    k_prep1 <<<NBLK_N, 256>>>(a1s, a1d);
    k_layer1<<<nb_w, 256>>>(b1);
    k_gemm2 <<<NBLK_N, 256>>>(W2, a2s, a2d);
    k_layer2<<<nb_w, 256>>>(b2, Wl1, bl1, Wl2, bl2, out);
}

// round 9
// speedup vs baseline: 1.2800x; 1.0622x over previous
#include <cuda_runtime.h>
#include <cuda_fp16.h>
#include <cstdint>
#include <cfloat>

#define N_NODES 100000
#define E_MAX   3200000
#define NBLK_N  ((N_NODES + 255) / 256)   // 391

// ---------------- scratch (device globals) -----------------------------------
__device__ __align__(16) float g_h1 [N_NODES * 16];   // fp32 h1 (coalesced use only)
__device__ __align__(16) uint4 g_h1h[N_NODES * 2];    // fp16 h1, 32B/row (gathered)
__device__ __align__(16) float g_x2 [N_NODES * 16];
__device__ __align__(16) uint4 g_h2p[N_NODES * 2];    // 10xfp16 h2 + fp32 as2, 32B/row
__device__ float g_as [N_NODES], g_ad [N_NODES];
__device__ float g_ad2[N_NODES];
__device__ int   g_esrc[E_MAX];            // CSR: src sorted by dst
__device__ int   g_off[N_NODES + 1];
__device__ int   g_cur[N_NODES];
__device__ int   g_deg[N_NODES];
__device__ int   g_bsum[512];
__device__ int   g_is64;

// ---------------- helpers ----------------------------------------------------
__device__ __forceinline__ float lrelu(float v) { return v > 0.f ? v : 0.2f * v; }

__device__ __forceinline__ unsigned int h2u(__half2 h) {
    return *reinterpret_cast<unsigned int*>(&h);
}
__device__ __forceinline__ __half2 u2h(unsigned int u) {
    return *reinterpret_cast<__half2*>(&u);
}

__device__ __forceinline__ void decode_edge(const unsigned int* __restrict__ w,
                                            int e, int E, int& s, int& d) {
    if (g_is64) { s = (int)w[2 * e]; d = (int)w[2 * (E + e)]; }
    else        { s = (int)w[e];     d = (int)w[E + e]; }
    s = (s < 0) ? 0 : (s >= N_NODES ? N_NODES - 1 : s);
    d = (d < 0) ? 0 : (d >= N_NODES ? N_NODES - 1 : d);
}

// ---------------- edge pipeline ----------------------------------------------
__global__ void k_detect(const unsigned int* __restrict__ w) {
    __shared__ int nz;
    if (threadIdx.x == 0) nz = 0;
    __syncthreads();
    int local = 0;
    for (int i = threadIdx.x; i < 4096; i += 256)
        if ((i & 1) && w[i] != 0u) local = 1;
    if (local) atomicOr(&nz, 1);
    __syncthreads();
    if (threadIdx.x == 0) g_is64 = (nz == 0) ? 1 : 0;
}

__global__ void k_zero() {
    int n = blockIdx.x * blockDim.x + threadIdx.x;
    if (n < N_NODES) g_deg[n] = 0;
}

__global__ void k_hist(const unsigned int* __restrict__ w, int E) {
    int e = blockIdx.x * blockDim.x + threadIdx.x;
    if (e >= E) return;
    int s, d;
    decode_edge(w, e, E, s, d);
    atomicAdd(&g_deg[d], 1);
}

__global__ __launch_bounds__(256) void k_scan_block() {
    __shared__ int s[256];
    int t = threadIdx.x;
    int i = blockIdx.x * 256 + t;
    int v = (i < N_NODES) ? g_deg[i] : 0;
    s[t] = v;
    __syncthreads();
    #pragma unroll
    for (int o = 1; o < 256; o <<= 1) {
        int u = (t >= o) ? s[t - o] : 0;
        __syncthreads();
        s[t] += u;
        __syncthreads();
    }
    if (i < N_NODES) g_off[i] = s[t] - v;
    if (t == 255) g_bsum[blockIdx.x] = s[255];
}

__global__ __launch_bounds__(512) void k_scan_top() {
    __shared__ int s[512];
    int t = threadIdx.x;
    int v = (t < NBLK_N) ? g_bsum[t] : 0;
    s[t] = v;
    __syncthreads();
    #pragma unroll
    for (int o = 1; o < 512; o <<= 1) {
        int u = (t >= o) ? s[t - o] : 0;
        __syncthreads();
        s[t] += u;
        __syncthreads();
    }
    if (t < NBLK_N) g_bsum[t] = s[t] - v;
}

__global__ void k_scan_add(int E) {
    int i = blockIdx.x * blockDim.x + threadIdx.x;
    if (i < N_NODES) {
        int v = g_off[i] + g_bsum[blockIdx.x];
        g_off[i] = v;
        g_cur[i] = v;
    }
    if (i == 0) g_off[N_NODES] = E;
}

__global__ void k_scatter(const unsigned int* __restrict__ w, int E) {
    int e = blockIdx.x * blockDim.x + threadIdx.x;
    if (e >= E) return;
    int s, d;
    decode_edge(w, e, E, s, d);
    int pos = atomicAdd(&g_cur[d], 1);
    g_esrc[pos] = s;
}

// ---------------- dense layers -----------------------------------------------
__global__ __launch_bounds__(256) void k_gemm1(const float* __restrict__ x,
                                               const float* __restrict__ W) {
    __shared__ float xs[32 * 128];
    __shared__ float ws[128 * 16];
    int t = threadIdx.x;
    int base = blockIdx.x * 32;
    for (int i = t; i < 128 * 16; i += 256) ws[i] = W[i];
    for (int i = t; i < 32 * 128; i += 256) {
        int node = base + (i >> 7);
        xs[i] = (node < N_NODES) ? x[(size_t)base * 128 + i] : 0.f;
    }
    __syncthreads();
    for (int o = t; o < 512; o += 256) {
        int ln = o >> 4, c = o & 15;
        int node = base + ln;
        if (node >= N_NODES) continue;
        float acc = 0.f;
        #pragma unroll 16
        for (int k = 0; k < 128; k++) acc += xs[ln * 128 + k] * ws[k * 16 + c];
        g_h1[node * 16 + c] = acc;
    }
}

// as/ad + fp16 quantized h1 row (32B)
__global__ void k_prep1(const float* __restrict__ a_s, const float* __restrict__ a_d) {
    int n = blockIdx.x * blockDim.x + threadIdx.x;
    if (n >= N_NODES) return;
    const float4* hp = (const float4*)&g_h1[n * 16];
    float as = 0.f, ad = 0.f;
    float4 h[4];
    #pragma unroll
    for (int i = 0; i < 4; i++) {
        h[i] = hp[i];
        as += h[i].x * a_s[4*i] + h[i].y * a_s[4*i+1] + h[i].z * a_s[4*i+2] + h[i].w * a_s[4*i+3];
        ad += h[i].x * a_d[4*i] + h[i].y * a_d[4*i+1] + h[i].z * a_d[4*i+2] + h[i].w * a_d[4*i+3];
    }
    g_as[n] = as; g_ad[n] = ad;
    uint4 r0, r1;
    r0.x = h2u(__floats2half2_rn(h[0].x, h[0].y));
    r0.y = h2u(__floats2half2_rn(h[0].z, h[0].w));
    r0.z = h2u(__floats2half2_rn(h[1].x, h[1].y));
    r0.w = h2u(__floats2half2_rn(h[1].z, h[1].w));
    r1.x = h2u(__floats2half2_rn(h[2].x, h[2].y));
    r1.y = h2u(__floats2half2_rn(h[2].z, h[2].w));
    r1.z = h2u(__floats2half2_rn(h[3].x, h[3].y));
    r1.w = h2u(__floats2half2_rn(h[3].z, h[3].w));
    g_h1h[n * 2]     = r0;
    g_h1h[n * 2 + 1] = r1;
}

__device__ __forceinline__ void acc8(float* acc, float w, uint4 r) {
    float2 f;
    f = __half22float2(u2h(r.x)); acc[0] += w*f.x; acc[1] += w*f.y;
    f = __half22float2(u2h(r.y)); acc[2] += w*f.x; acc[3] += w*f.y;
    f = __half22float2(u2h(r.z)); acc[4] += w*f.x; acc[5] += w*f.y;
    f = __half22float2(u2h(r.w)); acc[6] += w*f.x; acc[7] += w*f.y;
}

// ---------------- GAT layer 1: warp per dst, online softmax, fp16 gather ------
__global__ __launch_bounds__(256) void k_layer1(const float* __restrict__ b1) {
    __shared__ float sb1[16];
    if (threadIdx.x < 16) sb1[threadIdx.x] = b1[threadIdx.x];
    __syncthreads();
    int warp = (blockIdx.x * 256 + threadIdx.x) >> 5;
    int lane = threadIdx.x & 31;
    if (warp >= N_NODES) return;
    int beg = g_off[warp], end = g_off[warp + 1];
    float ad = g_ad[warp];

    float m, wsum;
    float acc[16];
    if (lane == 0) {
        m = lrelu(g_as[warp] + ad);
        wsum = 1.f;
        #pragma unroll
        for (int c = 0; c < 16; c++) acc[c] = 0.f;
        acc8(acc, 1.f, g_h1h[warp * 2]);
        acc8(acc + 8, 1.f, g_h1h[warp * 2 + 1]);
    } else {
        m = -FLT_MAX; wsum = 0.f;
        #pragma unroll
        for (int c = 0; c < 16; c++) acc[c] = 0.f;
    }

    for (int i = beg + lane; i < end; i += 32) {
        int s = g_esrc[i];
        float e = lrelu(g_as[s] + ad);
        float w;
        if (e > m) {
            float sc = __expf(m - e);
            wsum *= sc;
            #pragma unroll
            for (int c = 0; c < 16; c++) acc[c] *= sc;
            m = e; w = 1.f;
        } else {
            w = __expf(e - m);
        }
        wsum += w;
        uint4 r0 = g_h1h[s * 2], r1 = g_h1h[s * 2 + 1];
        acc8(acc, w, r0);
        acc8(acc + 8, w, r1);
    }

    #pragma unroll
    for (int o = 16; o; o >>= 1) {
        float mo = __shfl_xor_sync(0xffffffffu, m, o);
        float wo = __shfl_xor_sync(0xffffffffu, wsum, o);
        float M  = fmaxf(m, mo);
        float sa = __expf(m - M), sb = __expf(mo - M);
        wsum = wsum * sa + wo * sb;
        #pragma unroll
        for (int c = 0; c < 16; c++) {
            float ao = __shfl_xor_sync(0xffffffffu, acc[c], o);
            acc[c] = acc[c] * sa + ao * sb;
        }
        m = M;
    }

    if (lane == 0) {
        float inv = 1.f / wsum;
        #pragma unroll
        for (int c = 0; c < 16; c++) {
            float v = acc[c] * inv + sb1[c];
            g_x2[warp * 16 + c] = v > 0.f ? v : 0.f;
        }
    }
}

// h2 = x2 @ W2 (16 -> 10); packed 32B row: 10xfp16 + fp32 as2
__global__ __launch_bounds__(256) void k_gemm2(const float* __restrict__ W2,
                                               const float* __restrict__ a2s,
                                               const float* __restrict__ a2d) {
    __shared__ float ws[160], sas[10], sad[10];
    int t = threadIdx.x;
    if (t < 160) ws[t] = W2[t];
    if (t < 10) { sas[t] = a2s[t]; sad[t] = a2d[t]; }
    __syncthreads();
    int n = blockIdx.x * blockDim.x + t;
    if (n >= N_NODES) return;
    const float4* xp = (const float4*)&g_x2[n * 16];
    float hin[16];
    #pragma unroll
    for (int i = 0; i < 4; i++) {
        float4 v = xp[i];
        hin[4*i] = v.x; hin[4*i+1] = v.y; hin[4*i+2] = v.z; hin[4*i+3] = v.w;
    }
    float as = 0.f, ad = 0.f;
    float hv[10];
    #pragma unroll
    for (int j = 0; j < 10; j++) {
        float a = 0.f;
        #pragma unroll
        for (int k = 0; k < 16; k++) a += hin[k] * ws[k * 10 + j];
        hv[j] = a;
        as += a * sas[j]; ad += a * sad[j];
    }
    uint4 r0, r1;
    r0.x = h2u(__floats2half2_rn(hv[0], hv[1]));
    r0.y = h2u(__floats2half2_rn(hv[2], hv[3]));
    r0.z = h2u(__floats2half2_rn(hv[4], hv[5]));
    r0.w = h2u(__floats2half2_rn(hv[6], hv[7]));
    r1.x = h2u(__floats2half2_rn(hv[8], hv[9]));
    r1.y = __float_as_uint(as);
    r1.z = 0u; r1.w = 0u;
    g_h2p[n * 2]     = r0;
    g_h2p[n * 2 + 1] = r1;
    g_ad2[n] = ad;
}

// ---------------- GAT layer 2 (1 sector/edge) + fused output MLP --------------
__global__ __launch_bounds__(256) void k_layer2(const float* __restrict__ b2,
                                                const float* __restrict__ Wl1,
                                                const float* __restrict__ bl1,
                                                const float* __restrict__ Wl2,
                                                const float* __restrict__ bl2,
                                                float* __restrict__ out) {
    __shared__ float swl1[100], sbl1[10], swl2[10], sb2[10], sbl2;
    int t = threadIdx.x;
    if (t < 100) swl1[t] = Wl1[t];
    if (t < 10) { sbl1[t] = bl1[t]; swl2[t] = Wl2[t]; sb2[t] = b2[t]; }
    if (t == 0) sbl2 = bl2[0];
    __syncthreads();
    int warp = (blockIdx.x * 256 + t) >> 5;
    int lane = t & 31;
    if (warp >= N_NODES) return;
    int beg = g_off[warp], end = g_off[warp + 1];
    float ad = g_ad2[warp];

    float m, wsum;
    float acc[10];
    #pragma unroll
    for (int c = 0; c < 10; c++) acc[c] = 0.f;
    if (lane == 0) {
        uint4 r0 = g_h2p[warp * 2], r1 = g_h2p[warp * 2 + 1];
        float as2 = __uint_as_float(r1.y);
        m = lrelu(as2 + ad);
        wsum = 1.f;
        acc8(acc, 1.f, r0);
        float2 f = __half22float2(u2h(r1.x));
        acc[8] = f.x; acc[9] = f.y;
    } else {
        m = -FLT_MAX; wsum = 0.f;
    }

    for (int i = beg + lane; i < end; i += 32) {
        int s = g_esrc[i];
        uint4 r0 = g_h2p[s * 2], r1 = g_h2p[s * 2 + 1];
        float e = lrelu(__uint_as_float(r1.y) + ad);
        float w;
        if (e > m) {
            float sc = __expf(m - e);
            wsum *= sc;
            #pragma unroll
            for (int c = 0; c < 10; c++) acc[c] *= sc;
            m = e; w = 1.f;
        } else {
            w = __expf(e - m);
        }
        wsum += w;
        acc8(acc, w, r0);
        float2 f = __half22float2(u2h(r1.x));
        acc[8] += w * f.x; acc[9] += w * f.y;
    }

    #pragma unroll
    for (int o = 16; o; o >>= 1) {
        float mo = __shfl_xor_sync(0xffffffffu, m, o);
        float wo = __shfl_xor_sync(0xffffffffu, wsum, o);
        float M  = fmaxf(m, mo);
        float sa = __expf(m - M), sb = __expf(mo - M);
        wsum = wsum * sa + wo * sb;
        #pragma unroll
        for (int c = 0; c < 10; c++) {
            float ao = __shfl_xor_sync(0xffffffffu, acc[c], o);
            acc[c] = acc[c] * sa + ao * sb;
        }
        m = M;
    }

    if (lane == 0) {
        float inv = 1.f / wsum;
        float g[10];
        #pragma unroll
        for (int c = 0; c < 10; c++) g[c] = acc[c] * inv + sb2[c];
        float y = 0.f;
        #pragma unroll
        for (int j = 0; j < 10; j++) {
            float v = sbl1[j];
            #pragma unroll
            for (int c = 0; c < 10; c++) v += g[c] * swl1[c * 10 + j];
            v = v > 0.f ? v : 0.f;
            y += v * swl2[j];
        }
        out[warp] = y + sbl2;
    }
}

// ---------------- launch ------------------------------------------------------
extern "C" void kernel_launch(void* const* d_in, const int* in_sizes, int n_in,
                              void* d_out, int out_size) {
    const float*        x    = (const float*)d_in[0];
    const unsigned int* ei   = (const unsigned int*)d_in[1];
    const float*        W1   = (const float*)d_in[2];
    const float*        a1s  = (const float*)d_in[3];
    const float*        a1d  = (const float*)d_in[4];
    const float*        b1   = (const float*)d_in[5];
    const float*        W2   = (const float*)d_in[6];
    const float*        a2s  = (const float*)d_in[7];
    const float*        a2d  = (const float*)d_in[8];
    const float*        b2   = (const float*)d_in[9];
    const float*        Wl1  = (const float*)d_in[10];
    const float*        bl1  = (const float*)d_in[11];
    const float*        Wl2  = (const float*)d_in[12];
    const float*        bl2  = (const float*)d_in[13];
    float*              out  = (float*)d_out;

    int E = in_sizes[1] / 2;
    if (E > E_MAX) E = E_MAX;
    int nb_e = (E + 255) / 256;
    int nb_w = (N_NODES * 32 + 255) / 256;

    k_detect    <<<1, 256>>>(ei);
    k_zero      <<<NBLK_N, 256>>>();
    k_hist      <<<nb_e, 256>>>(ei, E);
    k_scan_block<<<NBLK_N, 256>>>();
    k_scan_top  <<<1, 512>>>();
    k_scan_add  <<<NBLK_N, 256>>>(E);
    k_scatter   <<<nb_e, 256>>>(ei, E);

    k_gemm1 <<<(N_NODES + 31) / 32, 256>>>(x, W1);
    k_prep1 <<<NBLK_N, 256>>>(a1s, a1d);
    k_layer1<<<nb_w, 256>>>(b1);
    k_gemm2 <<<NBLK_N, 256>>>(W2, a2s, a2d);
    k_layer2<<<nb_w, 256>>>(b2, Wl1, bl1, Wl2, bl2, out);
}

// round 11
// speedup vs baseline: 1.7643x; 1.3783x over previous
#include <cuda_runtime.h>
#include <cuda_fp16.h>
#include <cstdint>
#include <cfloat>

#define N_NODES 100000
#define E_MAX   3200000
#define NBLK_N  ((N_NODES + 255) / 256)   // 391
#define NBLK_W  6250                      // 8 warps/block, 2 nodes/warp -> 100000

// ---------------- scratch (device globals) -----------------------------------
__device__ __align__(16) float g_h1 [N_NODES * 16];   // fp32 h1 (coalesced use only)
__device__ __align__(16) uint4 g_h1h[N_NODES * 2];    // fp16 h1, 32B/row (gathered)
__device__ __align__(16) float g_x2 [N_NODES * 16];
__device__ __align__(16) uint4 g_h2p[N_NODES * 2];    // 10xfp16 h2 + fp32 as2, 32B/row
__device__ float g_as [N_NODES], g_ad [N_NODES];
__device__ float g_ad2[N_NODES];
__device__ int   g_esrc[E_MAX];            // CSR: src sorted by dst
__device__ int   g_off[N_NODES + 1];
__device__ int   g_cur[N_NODES];
__device__ int   g_deg[N_NODES];
__device__ int   g_bsum[512];
__device__ int   g_is64;

// ---------------- helpers ----------------------------------------------------
__device__ __forceinline__ float lrelu(float v) { return v > 0.f ? v : 0.2f * v; }

__device__ __forceinline__ unsigned int h2u(__half2 h) {
    return *reinterpret_cast<unsigned int*>(&h);
}

__device__ __forceinline__ void decode_edge(const unsigned int* __restrict__ w,
                                            int e, int E, int& s, int& d) {
    if (g_is64) { s = (int)w[2 * e]; d = (int)w[2 * (E + e)]; }
    else        { s = (int)w[e];     d = (int)w[E + e]; }
    s = (s < 0) ? 0 : (s >= N_NODES ? N_NODES - 1 : s);
    d = (d < 0) ? 0 : (d >= N_NODES ? N_NODES - 1 : d);
}

// ---------------- edge pipeline ----------------------------------------------
__global__ void k_detect(const unsigned int* __restrict__ w) {
    __shared__ int nz;
    if (threadIdx.x == 0) nz = 0;
    __syncthreads();
    int local = 0;
    for (int i = threadIdx.x; i < 4096; i += 256)
        if ((i & 1) && w[i] != 0u) local = 1;
    if (local) atomicOr(&nz, 1);
    __syncthreads();
    if (threadIdx.x == 0) g_is64 = (nz == 0) ? 1 : 0;
}

__global__ void k_zero() {
    int n = blockIdx.x * blockDim.x + threadIdx.x;
    if (n < N_NODES) g_deg[n] = 0;
}

__global__ void k_hist(const unsigned int* __restrict__ w, int E) {
    int e = blockIdx.x * blockDim.x + threadIdx.x;
    if (e >= E) return;
    int d;
    if (g_is64) d = (int)w[2 * (E + e)];
    else        d = (int)w[E + e];
    d = (d < 0) ? 0 : (d >= N_NODES ? N_NODES - 1 : d);
    atomicAdd(&g_deg[d], 1);
}

__global__ __launch_bounds__(256) void k_scan_block() {
    __shared__ int s[256];
    int t = threadIdx.x;
    int i = blockIdx.x * 256 + t;
    int v = (i < N_NODES) ? g_deg[i] : 0;
    s[t] = v;
    __syncthreads();
    #pragma unroll
    for (int o = 1; o < 256; o <<= 1) {
        int u = (t >= o) ? s[t - o] : 0;
        __syncthreads();
        s[t] += u;
        __syncthreads();
    }
    if (i < N_NODES) g_off[i] = s[t] - v;
    if (t == 255) g_bsum[blockIdx.x] = s[255];
}

__global__ __launch_bounds__(512) void k_scan_top() {
    __shared__ int s[512];
    int t = threadIdx.x;
    int v = (t < NBLK_N) ? g_bsum[t] : 0;
    s[t] = v;
    __syncthreads();
    #pragma unroll
    for (int o = 1; o < 512; o <<= 1) {
        int u = (t >= o) ? s[t - o] : 0;
        __syncthreads();
        s[t] += u;
        __syncthreads();
    }
    if (t < NBLK_N) g_bsum[t] = s[t] - v;
}

__global__ void k_scan_add(int E) {
    int i = blockIdx.x * blockDim.x + threadIdx.x;
    if (i < N_NODES) {
        int v = g_off[i] + g_bsum[blockIdx.x];
        g_off[i] = v;
        g_cur[i] = v;
    }
    if (i == 0) g_off[N_NODES] = E;
}

__global__ void k_scatter(const unsigned int* __restrict__ w, int E) {
    int e = blockIdx.x * blockDim.x + threadIdx.x;
    if (e >= E) return;
    int s, d;
    decode_edge(w, e, E, s, d);
    int pos = atomicAdd(&g_cur[d], 1);
    g_esrc[pos] = s;
}

// ---------------- dense layers -----------------------------------------------
__global__ __launch_bounds__(256) void k_gemm1(const float* __restrict__ x,
                                               const float* __restrict__ W) {
    __shared__ float xs[32 * 128];
    __shared__ float ws[128 * 16];
    int t = threadIdx.x;
    int base = blockIdx.x * 32;
    for (int i = t; i < 128 * 16; i += 256) ws[i] = W[i];
    for (int i = t; i < 32 * 128; i += 256) {
        int node = base + (i >> 7);
        xs[i] = (node < N_NODES) ? x[(size_t)base * 128 + i] : 0.f;
    }
    __syncthreads();
    for (int o = t; o < 512; o += 256) {
        int ln = o >> 4, c = o & 15;
        int node = base + ln;
        if (node >= N_NODES) continue;
        float acc = 0.f;
        #pragma unroll 16
        for (int k = 0; k < 128; k++) acc += xs[ln * 128 + k] * ws[k * 16 + c];
        g_h1[node * 16 + c] = acc;
    }
}

// as/ad + fp16 quantized h1 row (32B)
__global__ void k_prep1(const float* __restrict__ a_s, const float* __restrict__ a_d) {
    int n = blockIdx.x * blockDim.x + threadIdx.x;
    if (n >= N_NODES) return;
    const float4* hp = (const float4*)&g_h1[n * 16];
    float as = 0.f, ad = 0.f;
    float4 h[4];
    #pragma unroll
    for (int i = 0; i < 4; i++) {
        h[i] = hp[i];
        as += h[i].x * a_s[4*i] + h[i].y * a_s[4*i+1] + h[i].z * a_s[4*i+2] + h[i].w * a_s[4*i+3];
        ad += h[i].x * a_d[4*i] + h[i].y * a_d[4*i+1] + h[i].z * a_d[4*i+2] + h[i].w * a_d[4*i+3];
    }
    g_as[n] = as; g_ad[n] = ad;
    uint4 r0, r1;
    r0.x = h2u(__floats2half2_rn(h[0].x, h[0].y));
    r0.y = h2u(__floats2half2_rn(h[0].z, h[0].w));
    r0.z = h2u(__floats2half2_rn(h[1].x, h[1].y));
    r0.w = h2u(__floats2half2_rn(h[1].z, h[1].w));
    r1.x = h2u(__floats2half2_rn(h[2].x, h[2].y));
    r1.y = h2u(__floats2half2_rn(h[2].z, h[2].w));
    r1.z = h2u(__floats2half2_rn(h[3].x, h[3].y));
    r1.w = h2u(__floats2half2_rn(h[3].z, h[3].w));
    g_h1h[n * 2]     = r0;
    g_h1h[n * 2 + 1] = r1;
}

// ---------------- GAT layer 1: half-warp per node, lane = feature -------------
__global__ __launch_bounds__(256) void k_layer1(const float* __restrict__ b1) {
    __shared__ float sb1[16];
    __shared__ int   ss[8][32];
    __shared__ float sw[8][32];
    int t = threadIdx.x;
    if (t < 16) sb1[t] = b1[t];
    __syncthreads();
    int wid  = t >> 5;
    int lane = t & 31;
    int hb   = lane >> 4;          // half-warp id (0/1)
    int sl   = lane & 15;          // sub-lane = feature
    int gw   = blockIdx.x * 8 + wid;
    int node = gw * 2 + hb;        // exact: 6250*8*2 = 100000
    int beg = g_off[node], end = g_off[node + 1];
    int deg = end - beg;
    float ad = g_ad[node];

    const __half* hbase = (const __half*)g_h1h;

    // self-loop seed
    float m    = lrelu(g_as[node] + ad);
    float wsum = (sl == 0) ? 1.f : 0.f;
    float acc  = __half2float(hbase[node * 16 + sl]);

    int nch = (deg + 15) >> 4;
    int och = __shfl_xor_sync(0xffffffffu, nch, 16);
    int nmax = nch > och ? nch : och;

    for (int c = 0; c < nmax; c++) {
        int i = beg + c * 16 + sl;
        bool v = (i < end);
        int s = v ? g_esrc[i] : 0;
        float e = v ? lrelu(g_as[s] + ad) : -FLT_MAX;
        // half-warp max (offsets 1..8 stay within half)
        float em = e;
        #pragma unroll
        for (int o = 1; o <= 8; o <<= 1)
            em = fmaxf(em, __shfl_xor_sync(0xffffffffu, em, o));
        float M = fmaxf(m, em);
        float sc = __expf(m - M);
        wsum *= sc; acc *= sc; m = M;
        float w = v ? __expf(e - m) : 0.f;
        wsum += w;
        ss[wid][lane] = s;
        sw[wid][lane] = w;
        __syncwarp();
        int sbase = hb * 16;
        #pragma unroll 4
        for (int k = 0; k < 16; k++) {
            int   sk = ss[wid][sbase + k];
            float wk = sw[wid][sbase + k];
            acc += wk * __half2float(hbase[sk * 16 + sl]);
        }
        __syncwarp();
    }

    // half-warp sum of wsum
    #pragma unroll
    for (int o = 1; o <= 8; o <<= 1)
        wsum += __shfl_xor_sync(0xffffffffu, wsum, o);

    float v = acc / wsum + sb1[sl];
    g_x2[node * 16 + sl] = v > 0.f ? v : 0.f;
}

// h2 = x2 @ W2 (16 -> 10); packed 32B row: 10xfp16 (bytes 0-19) + fp32 as2 (20-23)
__global__ __launch_bounds__(256) void k_gemm2(const float* __restrict__ W2,
                                               const float* __restrict__ a2s,
                                               const float* __restrict__ a2d) {
    __shared__ float ws[160], sas[10], sad[10];
    int t = threadIdx.x;
    if (t < 160) ws[t] = W2[t];
    if (t < 10) { sas[t] = a2s[t]; sad[t] = a2d[t]; }
    __syncthreads();
    int n = blockIdx.x * blockDim.x + t;
    if (n >= N_NODES) return;
    const float4* xp = (const float4*)&g_x2[n * 16];
    float hin[16];
    #pragma unroll
    for (int i = 0; i < 4; i++) {
        float4 v = xp[i];
        hin[4*i] = v.x; hin[4*i+1] = v.y; hin[4*i+2] = v.z; hin[4*i+3] = v.w;
    }
    float as = 0.f, ad = 0.f;
    float hv[10];
    #pragma unroll
    for (int j = 0; j < 10; j++) {
        float a = 0.f;
        #pragma unroll
        for (int k = 0; k < 16; k++) a += hin[k] * ws[k * 10 + j];
        hv[j] = a;
        as += a * sas[j]; ad += a * sad[j];
    }
    uint4 r0, r1;
    r0.x = h2u(__floats2half2_rn(hv[0], hv[1]));
    r0.y = h2u(__floats2half2_rn(hv[2], hv[3]));
    r0.z = h2u(__floats2half2_rn(hv[4], hv[5]));
    r0.w = h2u(__floats2half2_rn(hv[6], hv[7]));
    r1.x = h2u(__floats2half2_rn(hv[8], hv[9]));
    r1.y = __float_as_uint(as);
    r1.z = 0u; r1.w = 0u;
    g_h2p[n * 2]     = r0;
    g_h2p[n * 2 + 1] = r1;
    g_ad2[n] = ad;
}

// ---------------- GAT layer 2 (feature-parallel) + fused output MLP -----------
__global__ __launch_bounds__(256) void k_layer2(const float* __restrict__ b2,
                                                const float* __restrict__ Wl1,
                                                const float* __restrict__ bl1,
                                                const float* __restrict__ Wl2,
                                                const float* __restrict__ bl2,
                                                float* __restrict__ out) {
    __shared__ float swl1[100], sbl1[16], swl2[16], sb2[16], sbl2;
    __shared__ int   ss[8][32];
    __shared__ float sw[8][32];
    int t = threadIdx.x;
    if (t < 100) swl1[t] = Wl1[t];
    if (t < 16) {
        sbl1[t] = (t < 10) ? bl1[t] : 0.f;
        swl2[t] = (t < 10) ? Wl2[t] : 0.f;
        sb2[t]  = (t < 10) ? b2[t]  : 0.f;
    }
    if (t == 0) sbl2 = bl2[0];
    __syncthreads();
    int wid  = t >> 5;
    int lane = t & 31;
    int hb   = lane >> 4;
    int sl   = lane & 15;
    int gw   = blockIdx.x * 8 + wid;
    int node = gw * 2 + hb;
    int beg = g_off[node], end = g_off[node + 1];
    int deg = end - beg;
    float ad = g_ad2[node];

    const __half*  hbase = (const __half*)g_h2p;
    const float*   fbase = (const float*)g_h2p;   // as2 at [row*8 + 5]

    float m    = lrelu(fbase[node * 8 + 5] + ad);
    float wsum = (sl == 0) ? 1.f : 0.f;
    float acc  = (sl < 10) ? __half2float(hbase[node * 16 + sl]) : 0.f;

    int nch = (deg + 15) >> 4;
    int och = __shfl_xor_sync(0xffffffffu, nch, 16);
    int nmax = nch > och ? nch : och;

    for (int c = 0; c < nmax; c++) {
        int i = beg + c * 16 + sl;
        bool v = (i < end);
        int s = v ? g_esrc[i] : 0;
        float e = v ? lrelu(fbase[s * 8 + 5] + ad) : -FLT_MAX;
        float em = e;
        #pragma unroll
        for (int o = 1; o <= 8; o <<= 1)
            em = fmaxf(em, __shfl_xor_sync(0xffffffffu, em, o));
        float M = fmaxf(m, em);
        float sc = __expf(m - M);
        wsum *= sc; acc *= sc; m = M;
        float w = v ? __expf(e - m) : 0.f;
        wsum += w;
        ss[wid][lane] = s;
        sw[wid][lane] = w;
        __syncwarp();
        int sbase = hb * 16;
        if (sl < 10) {
            #pragma unroll 4
            for (int k = 0; k < 16; k++) {
                int   sk = ss[wid][sbase + k];
                float wk = sw[wid][sbase + k];
                acc += wk * __half2float(hbase[sk * 16 + sl]);
            }
        }
        __syncwarp();
    }

    #pragma unroll
    for (int o = 1; o <= 8; o <<= 1)
        wsum += __shfl_xor_sync(0xffffffffu, wsum, o);

    // g_c distributed: lane sl holds g[sl] for sl<10
    float gval = acc / wsum + sb2[sl];   // junk for sl>=10, never broadcast

    // warp-parallel MLP: lane j computes v_j = relu(bl1_j + sum_c g_c Wl1[c][j])
    float vj = sbl1[sl];
    #pragma unroll
    for (int cc = 0; cc < 10; cc++) {
        float gc = __shfl_sync(0xffffffffu, gval, hb * 16 + cc);
        if (sl < 10) vj += gc * swl1[cc * 10 + sl];
    }
    vj = vj > 0.f ? vj : 0.f;
    float contrib = (sl < 10) ? vj * swl2[sl] : 0.f;
    #pragma unroll
    for (int o = 1; o <= 8; o <<= 1)
        contrib += __shfl_xor_sync(0xffffffffu, contrib, o);

    if (sl == 0) out[node] = contrib + sbl2;
}

// ---------------- launch ------------------------------------------------------
extern "C" void kernel_launch(void* const* d_in, const int* in_sizes, int n_in,
                              void* d_out, int out_size) {
    const float*        x    = (const float*)d_in[0];
    const unsigned int* ei   = (const unsigned int*)d_in[1];
    const float*        W1   = (const float*)d_in[2];
    const float*        a1s  = (const float*)d_in[3];
    const float*        a1d  = (const float*)d_in[4];
    const float*        b1   = (const float*)d_in[5];
    const float*        W2   = (const float*)d_in[6];
    const float*        a2s  = (const float*)d_in[7];
    const float*        a2d  = (const float*)d_in[8];
    const float*        b2   = (const float*)d_in[9];
    const float*        Wl1  = (const float*)d_in[10];
    const float*        bl1  = (const float*)d_in[11];
    const float*        Wl2  = (const float*)d_in[12];
    const float*        bl2  = (const float*)d_in[13];
    float*              out  = (float*)d_out;

    int E = in_sizes[1] / 2;
    if (E > E_MAX) E = E_MAX;
    int nb_e = (E + 255) / 256;

    k_detect    <<<1, 256>>>(ei);
    k_zero      <<<NBLK_N, 256>>>();
    k_hist      <<<nb_e, 256>>>(ei, E);
    k_scan_block<<<NBLK_N, 256>>>();
    k_scan_top  <<<1, 512>>>();
    k_scan_add  <<<NBLK_N, 256>>>(E);
    k_scatter   <<<nb_e, 256>>>(ei, E);

    k_gemm1 <<<(N_NODES + 31) / 32, 256>>>(x, W1);
    k_prep1 <<<NBLK_N, 256>>>(a1s, a1d);
    k_layer1<<<NBLK_W, 256>>>(b1);
    k_gemm2 <<<NBLK_N, 256>>>(W2, a2s, a2d);
    k_layer2<<<NBLK_W, 256>>>(b2, Wl1, bl1, Wl2, bl2, out);
}

// round 14
// speedup vs baseline: 1.7900x; 1.0146x over previous
#include <cuda_runtime.h>
#include <cuda_fp16.h>
#include <cstdint>
#include <cfloat>

#define N_NODES 100000
#define E_MAX   3200000
#define NBLK_N  ((N_NODES + 255) / 256)   // 391
#define NBLK_W  6250                      // 8 warps/block, 2 nodes/warp -> 100000

// ---------------- scratch (device globals) -----------------------------------
__device__ __align__(16) float g_h1 [N_NODES * 16];   // fp32 h1 (coalesced use only)
__device__ __align__(16) uint4 g_h1h[N_NODES * 2];    // fp16 h1, 32B/row (gathered)
__device__ __align__(16) float g_x2 [N_NODES * 16];
__device__ __align__(16) uint4 g_h2p[N_NODES * 2];    // 10xfp16 h2 + fp32 as2, 32B/row
__device__ float g_as [N_NODES], g_ad [N_NODES];
__device__ float g_ad2[N_NODES];
__device__ float g_gmax1, g_gmax2;         // global max of as / as2
__device__ int   g_esrc[E_MAX];            // CSR: src sorted by dst
__device__ int   g_off[N_NODES + 1];
__device__ int   g_cur[N_NODES];
__device__ int   g_deg[N_NODES];
__device__ int   g_bsum[512];
__device__ int   g_is64;

// ---------------- helpers ----------------------------------------------------
__device__ __forceinline__ float lrelu(float v) { return v > 0.f ? v : 0.2f * v; }

__device__ __forceinline__ unsigned int h2u(__half2 h) {
    return *reinterpret_cast<unsigned int*>(&h);
}

__device__ __forceinline__ void atomicMaxFloat(float* addr, float val) {
    if (val >= 0.f)
        atomicMax(reinterpret_cast<int*>(addr), __float_as_int(val));
    else
        atomicMin(reinterpret_cast<unsigned int*>(addr), __float_as_uint(val));
}

__device__ __forceinline__ void decode_edge(const unsigned int* __restrict__ w,
                                            int e, int E, int& s, int& d) {
    if (g_is64) { s = (int)w[2 * e]; d = (int)w[2 * (E + e)]; }
    else        { s = (int)w[e];     d = (int)w[E + e]; }
    s = (s < 0) ? 0 : (s >= N_NODES ? N_NODES - 1 : s);
    d = (d < 0) ? 0 : (d >= N_NODES ? N_NODES - 1 : d);
}

// ---------------- edge pipeline ----------------------------------------------
__global__ void k_detect(const unsigned int* __restrict__ w) {
    __shared__ int nz;
    if (threadIdx.x == 0) nz = 0;
    __syncthreads();
    int local = 0;
    for (int i = threadIdx.x; i < 4096; i += 256)
        if ((i & 1) && w[i] != 0u) local = 1;
    if (local) atomicOr(&nz, 1);
    __syncthreads();
    if (threadIdx.x == 0) {
        g_is64 = (nz == 0) ? 1 : 0;
        g_gmax1 = -FLT_MAX;
        g_gmax2 = -FLT_MAX;
    }
}

__global__ void k_zero() {
    int n = blockIdx.x * blockDim.x + threadIdx.x;
    if (n < N_NODES) g_deg[n] = 0;
}

__global__ void k_hist(const unsigned int* __restrict__ w, int E) {
    int e = blockIdx.x * blockDim.x + threadIdx.x;
    if (e >= E) return;
    int d;
    if (g_is64) d = (int)w[2 * (E + e)];
    else        d = (int)w[E + e];
    d = (d < 0) ? 0 : (d >= N_NODES ? N_NODES - 1 : d);
    atomicAdd(&g_deg[d], 1);
}

__global__ __launch_bounds__(256) void k_scan_block() {
    __shared__ int s[256];
    int t = threadIdx.x;
    int i = blockIdx.x * 256 + t;
    int v = (i < N_NODES) ? g_deg[i] : 0;
    s[t] = v;
    __syncthreads();
    #pragma unroll
    for (int o = 1; o < 256; o <<= 1) {
        int u = (t >= o) ? s[t - o] : 0;
        __syncthreads();
        s[t] += u;
        __syncthreads();
    }
    if (i < N_NODES) g_off[i] = s[t] - v;
    if (t == 255) g_bsum[blockIdx.x] = s[255];
}

__global__ __launch_bounds__(512) void k_scan_top() {
    __shared__ int s[512];
    int t = threadIdx.x;
    int v = (t < NBLK_N) ? g_bsum[t] : 0;
    s[t] = v;
    __syncthreads();
    #pragma unroll
    for (int o = 1; o < 512; o <<= 1) {
        int u = (t >= o) ? s[t - o] : 0;
        __syncthreads();
        s[t] += u;
        __syncthreads();
    }
    if (t < NBLK_N) g_bsum[t] = s[t] - v;
}

__global__ void k_scan_add(int E) {
    int i = blockIdx.x * blockDim.x + threadIdx.x;
    if (i < N_NODES) {
        int v = g_off[i] + g_bsum[blockIdx.x];
        g_off[i] = v;
        g_cur[i] = v;
    }
    if (i == 0) g_off[N_NODES] = E;
}

__global__ void k_scatter(const unsigned int* __restrict__ w, int E) {
    int e = blockIdx.x * blockDim.x + threadIdx.x;
    if (e >= E) return;
    int s, d;
    decode_edge(w, e, E, s, d);
    int pos = atomicAdd(&g_cur[d], 1);
    g_esrc[pos] = s;
}

// ---------------- dense layers -----------------------------------------------
__global__ __launch_bounds__(256) void k_gemm1(const float* __restrict__ x,
                                               const float* __restrict__ W) {
    __shared__ float xs[32 * 128];
    __shared__ float ws[128 * 16];
    int t = threadIdx.x;
    int base = blockIdx.x * 32;
    for (int i = t; i < 128 * 16; i += 256) ws[i] = W[i];
    for (int i = t; i < 32 * 128; i += 256) {
        int node = base + (i >> 7);
        xs[i] = (node < N_NODES) ? x[(size_t)base * 128 + i] : 0.f;
    }
    __syncthreads();
    for (int o = t; o < 512; o += 256) {
        int ln = o >> 4, c = o & 15;
        int node = base + ln;
        if (node >= N_NODES) continue;
        float acc = 0.f;
        #pragma unroll 16
        for (int k = 0; k < 128; k++) acc += xs[ln * 128 + k] * ws[k * 16 + c];
        g_h1[node * 16 + c] = acc;
    }
}

// as/ad + fp16 quantized h1 row (32B) + global max(as)
__global__ __launch_bounds__(256) void k_prep1(const float* __restrict__ a_s,
                                               const float* __restrict__ a_d) {
    __shared__ float smax[256];
    int t = threadIdx.x;
    int n = blockIdx.x * 256 + t;
    bool active = (n < N_NODES);
    float as = -FLT_MAX, ad = 0.f;
    if (active) {
        const float4* hp = (const float4*)&g_h1[n * 16];
        as = 0.f;
        float4 h[4];
        #pragma unroll
        for (int i = 0; i < 4; i++) {
            h[i] = hp[i];
            as += h[i].x * a_s[4*i] + h[i].y * a_s[4*i+1] + h[i].z * a_s[4*i+2] + h[i].w * a_s[4*i+3];
            ad += h[i].x * a_d[4*i] + h[i].y * a_d[4*i+1] + h[i].z * a_d[4*i+2] + h[i].w * a_d[4*i+3];
        }
        g_as[n] = as; g_ad[n] = ad;
        uint4 r0, r1;
        r0.x = h2u(__floats2half2_rn(h[0].x, h[0].y));
        r0.y = h2u(__floats2half2_rn(h[0].z, h[0].w));
        r0.z = h2u(__floats2half2_rn(h[1].x, h[1].y));
        r0.w = h2u(__floats2half2_rn(h[1].z, h[1].w));
        r1.x = h2u(__floats2half2_rn(h[2].x, h[2].y));
        r1.y = h2u(__floats2half2_rn(h[2].z, h[2].w));
        r1.z = h2u(__floats2half2_rn(h[3].x, h[3].y));
        r1.w = h2u(__floats2half2_rn(h[3].z, h[3].w));
        g_h1h[n * 2]     = r0;
        g_h1h[n * 2 + 1] = r1;
    }
    smax[t] = as;
    __syncthreads();
    #pragma unroll
    for (int o = 128; o; o >>= 1) {
        if (t < o) smax[t] = fmaxf(smax[t], smax[t + o]);
        __syncthreads();
    }
    if (t == 0) atomicMaxFloat(&g_gmax1, smax[0]);
}

// ---------------- GAT layer 1: half-warp per node, fixed bound m --------------
__global__ __launch_bounds__(256) void k_layer1(const float* __restrict__ b1) {
    __shared__ float sb1[16];
    __shared__ int2  spk[8][32];
    int t = threadIdx.x;
    if (t < 16) sb1[t] = b1[t];
    __syncthreads();
    int wid  = t >> 5;
    int lane = t & 31;
    int hb   = lane >> 4;          // half-warp id (0/1)
    int sl   = lane & 15;          // sub-lane = feature
    int gw   = blockIdx.x * 8 + wid;
    int node = gw * 2 + hb;        // exact: 6250*8*2 = 100000
    int beg = g_off[node], end = g_off[node + 1];
    int deg = end - beg;
    float ad = g_ad[node];
    float m  = lrelu(g_gmax1 + ad);      // per-dst upper bound, monotone in as

    const __half* hbase = (const __half*)g_h1h;

    // self-loop seed (every lane computes wself; only sl==0 counts it in wsum)
    float wself = __expf(lrelu(g_as[node] + ad) - m);
    float wsum  = (sl == 0) ? wself : 0.f;
    float acc   = wself * __half2float(hbase[node * 16 + sl]);

    int nch = (deg + 15) >> 4;
    int och = __shfl_xor_sync(0xffffffffu, nch, 16);
    int nmax = nch > och ? nch : och;

    for (int c = 0; c < nmax; c++) {
        int i = beg + c * 16 + sl;
        bool v = (i < end);
        int s = v ? g_esrc[i] : 0;
        float w = v ? __expf(lrelu(g_as[s] + ad) - m) : 0.f;
        wsum += w;
        spk[wid][lane] = make_int2(s, __float_as_int(w));
        __syncwarp();
        int sbase = hb * 16;
        #pragma unroll 4
        for (int k = 0; k < 16; k++) {
            int2  p  = spk[wid][sbase + k];
            float wk = __int_as_float(p.y);
            acc += wk * __half2float(hbase[p.x * 16 + sl]);
        }
        __syncwarp();
    }

    // half-warp sum of wsum
    #pragma unroll
    for (int o = 1; o <= 8; o <<= 1)
        wsum += __shfl_xor_sync(0xffffffffu, wsum, o);

    float v = acc / wsum + sb1[sl];
    g_x2[node * 16 + sl] = v > 0.f ? v : 0.f;
}

// h2 = x2 @ W2 (16 -> 10); packed 32B row: 10xfp16 + fp32 as2; + global max(as2)
__global__ __launch_bounds__(256) void k_gemm2(const float* __restrict__ W2,
                                               const float* __restrict__ a2s,
                                               const float* __restrict__ a2d) {
    __shared__ float ws[160], sas[10], sad[10];
    __shared__ float smax[256];
    int t = threadIdx.x;
    if (t < 160) ws[t] = W2[t];
    if (t < 10) { sas[t] = a2s[t]; sad[t] = a2d[t]; }
    __syncthreads();
    int n = blockIdx.x * blockDim.x + t;
    bool active = (n < N_NODES);
    float as = -FLT_MAX;
    if (active) {
        const float4* xp = (const float4*)&g_x2[n * 16];
        float hin[16];
        #pragma unroll
        for (int i = 0; i < 4; i++) {
            float4 v = xp[i];
            hin[4*i] = v.x; hin[4*i+1] = v.y; hin[4*i+2] = v.z; hin[4*i+3] = v.w;
        }
        float ad = 0.f;
        as = 0.f;
        float hv[10];
        #pragma unroll
        for (int j = 0; j < 10; j++) {
            float a = 0.f;
            #pragma unroll
            for (int k = 0; k < 16; k++) a += hin[k] * ws[k * 10 + j];
            hv[j] = a;
            as += a * sas[j]; ad += a * sad[j];
        }
        uint4 r0, r1;
        r0.x = h2u(__floats2half2_rn(hv[0], hv[1]));
        r0.y = h2u(__floats2half2_rn(hv[2], hv[3]));
        r0.z = h2u(__floats2half2_rn(hv[4], hv[5]));
        r0.w = h2u(__floats2half2_rn(hv[6], hv[7]));
        r1.x = h2u(__floats2half2_rn(hv[8], hv[9]));
        r1.y = __float_as_uint(as);
        r1.z = 0u; r1.w = 0u;
        g_h2p[n * 2]     = r0;
        g_h2p[n * 2 + 1] = r1;
        g_ad2[n] = ad;
    }
    smax[t] = as;
    __syncthreads();
    #pragma unroll
    for (int o = 128; o; o >>= 1) {
        if (t < o) smax[t] = fmaxf(smax[t], smax[t + o]);
        __syncthreads();
    }
    if (t == 0) atomicMaxFloat(&g_gmax2, smax[0]);
}

// ---------------- GAT layer 2 (feature-parallel) + fused output MLP -----------
__global__ __launch_bounds__(256) void k_layer2(const float* __restrict__ b2,
                                                const float* __restrict__ Wl1,
                                                const float* __restrict__ bl1,
                                                const float* __restrict__ Wl2,
                                                const float* __restrict__ bl2,
                                                float* __restrict__ out) {
    __shared__ float swl1[100], sbl1[16], swl2[16], sb2[16], sbl2;
    __shared__ int2  spk[8][32];
    int t = threadIdx.x;
    if (t < 100) swl1[t] = Wl1[t];
    if (t < 16) {
        sbl1[t] = (t < 10) ? bl1[t] : 0.f;
        swl2[t] = (t < 10) ? Wl2[t] : 0.f;
        sb2[t]  = (t < 10) ? b2[t]  : 0.f;
    }
    if (t == 0) sbl2 = bl2[0];
    __syncthreads();
    int wid  = t >> 5;
    int lane = t & 31;
    int hb   = lane >> 4;
    int sl   = lane & 15;
    int gw   = blockIdx.x * 8 + wid;
    int node = gw * 2 + hb;
    int beg = g_off[node], end = g_off[node + 1];
    int deg = end - beg;
    float ad = g_ad2[node];
    float m  = lrelu(g_gmax2 + ad);

    const __half* hbase = (const __half*)g_h2p;
    const float*  fbase = (const float*)g_h2p;   // as2 at [row*8 + 5]

    float wself = __expf(lrelu(fbase[node * 8 + 5] + ad) - m);
    float wsum  = (sl == 0) ? wself : 0.f;
    float acc   = (sl < 10) ? wself * __half2float(hbase[node * 16 + sl]) : 0.f;

    int nch = (deg + 15) >> 4;
    int och = __shfl_xor_sync(0xffffffffu, nch, 16);
    int nmax = nch > och ? nch : och;

    for (int c = 0; c < nmax; c++) {
        int i = beg + c * 16 + sl;
        bool v = (i < end);
        int s = v ? g_esrc[i] : 0;
        float w = v ? __expf(lrelu(fbase[s * 8 + 5] + ad) - m) : 0.f;
        wsum += w;
        spk[wid][lane] = make_int2(s, __float_as_int(w));
        __syncwarp();
        int sbase = hb * 16;
        if (sl < 10) {
            #pragma unroll 4
            for (int k = 0; k < 16; k++) {
                int2  p  = spk[wid][sbase + k];
                float wk = __int_as_float(p.y);
                acc += wk * __half2float(hbase[p.x * 16 + sl]);
            }
        }
        __syncwarp();
    }

    #pragma unroll
    for (int o = 1; o <= 8; o <<= 1)
        wsum += __shfl_xor_sync(0xffffffffu, wsum, o);

    // g_c distributed: lane sl holds g[sl] for sl<10
    float gval = acc / wsum + sb2[sl];   // junk for sl>=10, never broadcast

    // warp-parallel MLP: lane j computes v_j = relu(bl1_j + sum_c g_c Wl1[c][j])
    float vj = sbl1[sl];
    #pragma unroll
    for (int cc = 0; cc < 10; cc++) {
        float gc = __shfl_sync(0xffffffffu, gval, hb * 16 + cc);
        if (sl < 10) vj += gc * swl1[cc * 10 + sl];
    }
    vj = vj > 0.f ? vj : 0.f;
    float contrib = (sl < 10) ? vj * swl2[sl] : 0.f;
    #pragma unroll
    for (int o = 1; o <= 8; o <<= 1)
        contrib += __shfl_xor_sync(0xffffffffu, contrib, o);

    if (sl == 0) out[node] = contrib + sbl2;
}

// ---------------- launch ------------------------------------------------------
extern "C" void kernel_launch(void* const* d_in, const int* in_sizes, int n_in,
                              void* d_out, int out_size) {
    const float*        x    = (const float*)d_in[0];
    const unsigned int* ei   = (const unsigned int*)d_in[1];
    const float*        W1   = (const float*)d_in[2];
    const float*        a1s  = (const float*)d_in[3];
    const float*        a1d  = (const float*)d_in[4];
    const float*        b1   = (const float*)d_in[5];
    const float*        W2   = (const float*)d_in[6];
    const float*        a2s  = (const float*)d_in[7];
    const float*        a2d  = (const float*)d_in[8];
    const float*        b2   = (const float*)d_in[9];
    const float*        Wl1  = (const float*)d_in[10];
    const float*        bl1  = (const float*)d_in[11];
    const float*        Wl2  = (const float*)d_in[12];
    const float*        bl2  = (const float*)d_in[13];
    float*              out  = (float*)d_out;

    int E = in_sizes[1] / 2;
    if (E > E_MAX) E = E_MAX;
    int nb_e = (E + 255) / 256;

    k_detect    <<<1, 256>>>(ei);
    k_zero      <<<NBLK_N, 256>>>();
    k_hist      <<<nb_e, 256>>>(ei, E);
    k_scan_block<<<NBLK_N, 256>>>();
    k_scan_top  <<<1, 512>>>();
    k_scan_add  <<<NBLK_N, 256>>>(E);
    k_scatter   <<<nb_e, 256>>>(ei, E);

    k_gemm1 <<<(N_NODES + 31) / 32, 256>>>(x, W1);
    k_prep1 <<<NBLK_N, 256>>>(a1s, a1d);
    k_layer1<<<NBLK_W, 256>>>(b1);
    k_gemm2 <<<NBLK_N, 256>>>(W2, a2s, a2d);
    k_layer2<<<NBLK_W, 256>>>(b2, Wl1, bl1, Wl2, bl2, out);
}